// round 1
// baseline (speedup 1.0000x reference)
#include <cuda_runtime.h>
#include <math.h>

#define NN 50000
#define EE 800000
#define DD 128
#define BN_EPS 1e-5f

// ---------------- scratch (static device globals; no allocation) -------------
__device__ float g_deg[NN];
__device__ float g_dis[NN];
__device__ int   g_cnt[NN];
__device__ int   g_off[NN];
__device__ int   g_cur[NN];
__device__ int   g_src[EE];
__device__ float g_wn [EE];
__device__ float g_h  [NN * DD];   // emb @ W0
__device__ float g_h1 [NN * DD];   // after agg1 + BN + ELU
__device__ float g_g  [NN * DD];   // h1 @ W1

// ---------------- norm + CSC build ------------------------------------------
__global__ void k_init() {
    int i = blockIdx.x * blockDim.x + threadIdx.x;
    if (i < NN) { g_deg[i] = 1.0f; g_cnt[i] = 0; }   // 1.0 = self-loop weight
}

__global__ void k_deg(const int* __restrict__ col, const float* __restrict__ w) {
    int e = blockIdx.x * blockDim.x + threadIdx.x;
    if (e < EE) {
        int c = col[e];
        atomicAdd(&g_deg[c], w[e]);
        atomicAdd(&g_cnt[c], 1);
    }
}

__global__ void k_dis() {
    int i = blockIdx.x * blockDim.x + threadIdx.x;
    if (i < NN) g_dis[i] = rsqrtf(g_deg[i]);   // deg >= 1 always (self loop)
}

// single-block exclusive scan of g_cnt -> g_off, also initializes g_cur
__global__ void k_scan() {
    __shared__ int sums[1024];
    const int CH = 49;                 // 1024*49 >= 50000
    int t = threadIdx.x;
    int base = t * CH;
    int s = 0;
    for (int j = 0; j < CH; j++) {
        int idx = base + j;
        if (idx < NN) s += g_cnt[idx];
    }
    sums[t] = s;
    __syncthreads();
    for (int d = 1; d < 1024; d <<= 1) {
        int v = (t >= d) ? sums[t - d] : 0;
        __syncthreads();
        sums[t] += v;
        __syncthreads();
    }
    int run = (t == 0) ? 0 : sums[t - 1];
    for (int j = 0; j < CH; j++) {
        int idx = base + j;
        if (idx < NN) {
            g_off[idx] = run;
            g_cur[idx] = run;
            run += g_cnt[idx];
        }
    }
}

__global__ void k_scatter(const int* __restrict__ row, const int* __restrict__ col,
                          const float* __restrict__ w) {
    int e = blockIdx.x * blockDim.x + threadIdx.x;
    if (e < EE) {
        int r = row[e], c = col[e];
        int p = atomicAdd(&g_cur[c], 1);
        g_src[p] = r;
        g_wn[p]  = g_dis[r] * w[e] * g_dis[c];
    }
}

// ---------------- FP32 GEMM: C[M,128] = A[M,128] @ B[128,128] ----------------
// tile: 128 rows x 64 cols per block, 256 threads, 8x4 microtile per thread
__global__ __launch_bounds__(256) void k_gemm(const float* __restrict__ A_ext,
                                              const float* __restrict__ B,
                                              int sel) {
    __shared__ float As[16][128];   // k-major (transposed) A tile
    __shared__ float Bs[16][64];

    const float* A = A_ext ? A_ext : g_h1;
    float* C = (sel == 0) ? g_h : g_g;

    int tid = threadIdx.x;
    int tx = tid & 15;          // 0..15 -> col quad
    int ty = tid >> 4;          // 0..15 -> row octet
    int rowBase = blockIdx.x * 128;
    int colBase = blockIdx.y * 64;
    int r0 = ty * 8;
    int c0 = tx * 4;

    float acc[8][4];
#pragma unroll
    for (int i = 0; i < 8; i++)
#pragma unroll
        for (int j = 0; j < 4; j++) acc[i][j] = 0.0f;

    for (int kk = 0; kk < 128; kk += 16) {
        __syncthreads();
        // load A tile (128 rows x 16 k), store transposed into As[k][row]
#pragma unroll
        for (int i = 0; i < 2; i++) {
            int idx = tid * 2 + i;          // 0..511
            int r   = idx >> 2;             // 0..127
            int kq  = idx & 3;              // float4 within the 16-k strip
            int grow = rowBase + r;
            float4 v = make_float4(0.f, 0.f, 0.f, 0.f);
            if (grow < NN) v = *(const float4*)(A + grow * 128 + kk + kq * 4);
            As[kq * 4 + 0][r] = v.x;
            As[kq * 4 + 1][r] = v.y;
            As[kq * 4 + 2][r] = v.z;
            As[kq * 4 + 3][r] = v.w;
        }
        // load B tile (16 k x 64 n)
        {
            int k  = tid >> 4;
            int nq = tid & 15;
            float4 v = *(const float4*)(B + (kk + k) * 128 + colBase + nq * 4);
            *(float4*)&Bs[k][nq * 4] = v;
        }
        __syncthreads();
#pragma unroll
        for (int k = 0; k < 16; k++) {
            float a[8], b[4];
            *(float4*)&a[0] = *(const float4*)&As[k][r0];
            *(float4*)&a[4] = *(const float4*)&As[k][r0 + 4];
            *(float4*)&b[0] = *(const float4*)&Bs[k][c0];
#pragma unroll
            for (int i = 0; i < 8; i++)
#pragma unroll
                for (int j = 0; j < 4; j++) acc[i][j] += a[i] * b[j];
        }
    }

#pragma unroll
    for (int i = 0; i < 8; i++) {
        int grow = rowBase + r0 + i;
        if (grow < NN) {
            float4 v = make_float4(acc[i][0], acc[i][1], acc[i][2], acc[i][3]);
            *(float4*)(C + grow * 128 + colBase + c0) = v;
        }
    }
}

// ---------------- aggregation 1: conv1 + bias + BN + ELU ---------------------
__global__ void k_agg1(const float* __restrict__ b0,
                       const float* __restrict__ gamma,
                       const float* __restrict__ beta,
                       const float* __restrict__ mean,
                       const float* __restrict__ var) {
    int i = blockIdx.x;
    int f = threadIdx.x;
    const float* __restrict__ H = g_h;

    float di = g_dis[i];
    float acc0 = di * di * H[i * DD + f];   // self loop
    float acc1 = 0.f, acc2 = 0.f, acc3 = 0.f;

    int s = g_off[i];
    int n = g_cnt[i];
    int p = 0;
    for (; p + 4 <= n; p += 4) {
        int   i0 = g_src[s + p + 0], i1 = g_src[s + p + 1];
        int   i2 = g_src[s + p + 2], i3 = g_src[s + p + 3];
        float w0 = g_wn[s + p + 0],  w1 = g_wn[s + p + 1];
        float w2 = g_wn[s + p + 2],  w3 = g_wn[s + p + 3];
        acc0 += w0 * H[i0 * DD + f];
        acc1 += w1 * H[i1 * DD + f];
        acc2 += w2 * H[i2 * DD + f];
        acc3 += w3 * H[i3 * DD + f];
    }
    for (; p < n; p++)
        acc0 += g_wn[s + p] * H[g_src[s + p] * DD + f];

    float acc = ((acc0 + acc1) + (acc2 + acc3)) + b0[f];
    float sc  = gamma[f] * rsqrtf(var[f] + BN_EPS);
    float y   = (acc - mean[f]) * sc + beta[f];
    g_h1[i * DD + f] = (y > 0.f) ? y : expm1f(y);
}

// ---------------- aggregation 2 + final fusion mean --------------------------
__global__ void k_agg2(const float* __restrict__ emb,
                       const float* __restrict__ b1,
                       float* __restrict__ out) {
    int i = blockIdx.x;
    int f = threadIdx.x;
    const float* __restrict__ G = g_g;

    float di = g_dis[i];
    float acc0 = di * di * G[i * DD + f];
    float acc1 = 0.f, acc2 = 0.f, acc3 = 0.f;

    int s = g_off[i];
    int n = g_cnt[i];
    int p = 0;
    for (; p + 4 <= n; p += 4) {
        int   i0 = g_src[s + p + 0], i1 = g_src[s + p + 1];
        int   i2 = g_src[s + p + 2], i3 = g_src[s + p + 3];
        float w0 = g_wn[s + p + 0],  w1 = g_wn[s + p + 1];
        float w2 = g_wn[s + p + 2],  w3 = g_wn[s + p + 3];
        acc0 += w0 * G[i0 * DD + f];
        acc1 += w1 * G[i1 * DD + f];
        acc2 += w2 * G[i2 * DD + f];
        acc3 += w3 * G[i3 * DD + f];
    }
    for (; p < n; p++)
        acc0 += g_wn[s + p] * G[g_src[s + p] * DD + f];

    float h2 = ((acc0 + acc1) + (acc2 + acc3)) + b1[f];
    out[i * DD + f] = (emb[i * DD + f] + g_h1[i * DD + f] + h2) * (1.0f / 3.0f);
}

// ---------------- launch -----------------------------------------------------
extern "C" void kernel_launch(void* const* d_in, const int* in_sizes, int n_in,
                              void* d_out, int out_size) {
    const float* emb   = (const float*)d_in[0];
    const int*   ei    = (const int*)  d_in[1];
    const float* ew    = (const float*)d_in[2];
    const float* W0    = (const float*)d_in[3];
    const float* b0    = (const float*)d_in[4];
    const float* W1    = (const float*)d_in[5];
    const float* b1    = (const float*)d_in[6];
    const float* gamma = (const float*)d_in[7];
    const float* beta  = (const float*)d_in[8];
    const float* mean  = (const float*)d_in[9];
    const float* var   = (const float*)d_in[10];
    float* out = (float*)d_out;

    const int* row = ei;        // edge_index[0]
    const int* col = ei + EE;   // edge_index[1]

    const int NB_N = (NN + 255) / 256;
    const int NB_E = (EE + 255) / 256;

    k_init<<<NB_N, 256>>>();
    k_deg <<<NB_E, 256>>>(col, ew);
    k_dis <<<NB_N, 256>>>();
    k_scan<<<1, 1024>>>();
    k_scatter<<<NB_E, 256>>>(row, col, ew);

    dim3 ggrid((NN + 127) / 128, 2);
    k_gemm<<<ggrid, 256>>>(emb, W0, 0);          // g_h = emb @ W0
    k_agg1<<<NN, DD>>>(b0, gamma, beta, mean, var);
    k_gemm<<<ggrid, 256>>>(nullptr, W1, 1);      // g_g = g_h1 @ W1
    k_agg2<<<NN, DD>>>(emb, b1, out);
}

// round 2
// speedup vs baseline: 1.2763x; 1.2763x over previous
#include <cuda_runtime.h>
#include <math.h>

#define NN 50000
#define EE 800000
#define DD 128
#define BN_EPS 1e-5f
#define NSCAN_BLK 196   // ceil(50000/256)

// ---------------- scratch (static device globals; no allocation) -------------
__device__ float g_deg[NN];
__device__ float g_dis[NN];
__device__ int   g_cnt[NN];
__device__ int   g_off[NN];
__device__ int   g_cur[NN];
__device__ int   g_bsum[256];
__device__ int   g_boff[256];
__device__ int   g_src[EE];
__device__ float g_wn [EE];
__device__ float g_h  [NN * DD];   // emb @ W0
__device__ float g_h1 [NN * DD];   // after agg1 + BN + ELU
__device__ float g_g  [NN * DD];   // h1 @ W1

// ---------------- norm + CSC build ------------------------------------------
__global__ void k_init() {
    int i = blockIdx.x * blockDim.x + threadIdx.x;
    if (i < NN) { g_deg[i] = 1.0f; g_cnt[i] = 0; }   // 1.0 = self-loop weight
}

__global__ void k_deg(const int* __restrict__ col, const float* __restrict__ w) {
    int e = blockIdx.x * blockDim.x + threadIdx.x;
    if (e < EE) {
        int c = col[e];
        atomicAdd(&g_deg[c], w[e]);
        atomicAdd(&g_cnt[c], 1);
    }
}

// per-block sum of counts (scan level 1) + fused deg^-1/2
__global__ void k_bsum() {
    int i = blockIdx.x * 256 + threadIdx.x;
    int v = (i < NN) ? g_cnt[i] : 0;
    if (i < NN) g_dis[i] = rsqrtf(g_deg[i]);   // deg >= 1 (self loop)

#pragma unroll
    for (int o = 16; o > 0; o >>= 1) v += __shfl_down_sync(0xffffffffu, v, o);
    __shared__ int ws[8];
    int lane = threadIdx.x & 31, wid = threadIdx.x >> 5;
    if (lane == 0) ws[wid] = v;
    __syncthreads();
    if (threadIdx.x < 8) {
        int s = ws[threadIdx.x];
#pragma unroll
        for (int o = 4; o > 0; o >>= 1) s += __shfl_down_sync(0xffu, s, o);
        if (threadIdx.x == 0) g_bsum[blockIdx.x] = s;
    }
}

// scan level 2: exclusive scan of the 196 block sums (1 block)
__global__ void k_bscan() {
    __shared__ int sh[256];
    int t = threadIdx.x;
    int v = (t < NSCAN_BLK) ? g_bsum[t] : 0;
    sh[t] = v;
    __syncthreads();
#pragma unroll
    for (int d = 1; d < 256; d <<= 1) {
        int u = (t >= d) ? sh[t - d] : 0;
        __syncthreads();
        sh[t] += u;
        __syncthreads();
    }
    if (t < NSCAN_BLK) g_boff[t] = sh[t] - v;   // exclusive
}

// scan level 3: block-local exclusive scan + global offset -> g_off / g_cur
__global__ void k_scan3() {
    int i = blockIdx.x * 256 + threadIdx.x;
    int v = (i < NN) ? g_cnt[i] : 0;
    int lane = threadIdx.x & 31, wid = threadIdx.x >> 5;

    // inclusive warp scan
    int x = v;
#pragma unroll
    for (int o = 1; o < 32; o <<= 1) {
        int y = __shfl_up_sync(0xffffffffu, x, o);
        if (lane >= o) x += y;
    }
    __shared__ int wsum[8];
    if (lane == 31) wsum[wid] = x;
    __syncthreads();
    if (threadIdx.x < 8) {
        int s = wsum[threadIdx.x];
#pragma unroll
        for (int o = 1; o < 8; o <<= 1) {
            int y = __shfl_up_sync(0xffu, s, o);
            if ((int)threadIdx.x >= o) s += y;
        }
        wsum[threadIdx.x] = s;   // inclusive over warp totals
    }
    __syncthreads();
    int base = g_boff[blockIdx.x] + ((wid > 0) ? wsum[wid - 1] : 0);
    int excl = base + x - v;
    if (i < NN) { g_off[i] = excl; g_cur[i] = excl; }
}

__global__ void k_scatter(const int* __restrict__ row, const int* __restrict__ col,
                          const float* __restrict__ w) {
    int e = blockIdx.x * blockDim.x + threadIdx.x;
    if (e < EE) {
        int r = row[e], c = col[e];
        int p = atomicAdd(&g_cur[c], 1);
        g_src[p] = r;
        g_wn[p]  = g_dis[r] * w[e] * g_dis[c];
    }
}

// ---------------- FP32 GEMM: C[M,128] = A[M,128] @ B[128,128] ----------------
// tile: 128 rows x 64 cols per block, 256 threads, 8x4 microtile per thread
__global__ __launch_bounds__(256) void k_gemm(const float* __restrict__ A_ext,
                                              const float* __restrict__ B,
                                              int sel) {
    __shared__ float As[16][128];   // k-major (transposed) A tile
    __shared__ float Bs[16][64];

    const float* A = A_ext ? A_ext : g_h1;
    float* C = (sel == 0) ? g_h : g_g;

    int tid = threadIdx.x;
    int tx = tid & 15;          // 0..15 -> col quad
    int ty = tid >> 4;          // 0..15 -> row octet
    int rowBase = blockIdx.x * 128;
    int colBase = blockIdx.y * 64;
    int r0 = ty * 8;
    int c0 = tx * 4;

    float acc[8][4];
#pragma unroll
    for (int i = 0; i < 8; i++)
#pragma unroll
        for (int j = 0; j < 4; j++) acc[i][j] = 0.0f;

    for (int kk = 0; kk < 128; kk += 16) {
        __syncthreads();
#pragma unroll
        for (int i = 0; i < 2; i++) {
            int idx = tid * 2 + i;          // 0..511
            int r   = idx >> 2;             // 0..127
            int kq  = idx & 3;              // float4 within the 16-k strip
            int grow = rowBase + r;
            float4 v = make_float4(0.f, 0.f, 0.f, 0.f);
            if (grow < NN) v = *(const float4*)(A + grow * 128 + kk + kq * 4);
            As[kq * 4 + 0][r] = v.x;
            As[kq * 4 + 1][r] = v.y;
            As[kq * 4 + 2][r] = v.z;
            As[kq * 4 + 3][r] = v.w;
        }
        {
            int k  = tid >> 4;
            int nq = tid & 15;
            float4 v = *(const float4*)(B + (kk + k) * 128 + colBase + nq * 4);
            *(float4*)&Bs[k][nq * 4] = v;
        }
        __syncthreads();
#pragma unroll
        for (int k = 0; k < 16; k++) {
            float a[8], b[4];
            *(float4*)&a[0] = *(const float4*)&As[k][r0];
            *(float4*)&a[4] = *(const float4*)&As[k][r0 + 4];
            *(float4*)&b[0] = *(const float4*)&Bs[k][c0];
#pragma unroll
            for (int i = 0; i < 8; i++)
#pragma unroll
                for (int j = 0; j < 4; j++) acc[i][j] += a[i] * b[j];
        }
    }

#pragma unroll
    for (int i = 0; i < 8; i++) {
        int grow = rowBase + r0 + i;
        if (grow < NN) {
            float4 v = make_float4(acc[i][0], acc[i][1], acc[i][2], acc[i][3]);
            *(float4*)(C + grow * 128 + colBase + c0) = v;
        }
    }
}

// ---------------- aggregation 1: conv1 + bias + BN + ELU ---------------------
__global__ void k_agg1(const float* __restrict__ b0,
                       const float* __restrict__ gamma,
                       const float* __restrict__ beta,
                       const float* __restrict__ mean,
                       const float* __restrict__ var) {
    int i = blockIdx.x;
    int f = threadIdx.x;
    const float* __restrict__ H = g_h;

    float di = g_dis[i];
    float acc0 = di * di * H[i * DD + f];   // self loop
    float acc1 = 0.f, acc2 = 0.f, acc3 = 0.f;

    int s = g_off[i];
    int n = g_cnt[i];
    int p = 0;
    for (; p + 4 <= n; p += 4) {
        int   i0 = g_src[s + p + 0], i1 = g_src[s + p + 1];
        int   i2 = g_src[s + p + 2], i3 = g_src[s + p + 3];
        float w0 = g_wn[s + p + 0],  w1 = g_wn[s + p + 1];
        float w2 = g_wn[s + p + 2],  w3 = g_wn[s + p + 3];
        acc0 += w0 * H[i0 * DD + f];
        acc1 += w1 * H[i1 * DD + f];
        acc2 += w2 * H[i2 * DD + f];
        acc3 += w3 * H[i3 * DD + f];
    }
    for (; p < n; p++)
        acc0 += g_wn[s + p] * H[g_src[s + p] * DD + f];

    float acc = ((acc0 + acc1) + (acc2 + acc3)) + b0[f];
    float sc  = gamma[f] * rsqrtf(var[f] + BN_EPS);
    float y   = (acc - mean[f]) * sc + beta[f];
    g_h1[i * DD + f] = (y > 0.f) ? y : expm1f(y);
}

// ---------------- aggregation 2 + final fusion mean --------------------------
__global__ void k_agg2(const float* __restrict__ emb,
                       const float* __restrict__ b1,
                       float* __restrict__ out) {
    int i = blockIdx.x;
    int f = threadIdx.x;
    const float* __restrict__ G = g_g;

    float di = g_dis[i];
    float acc0 = di * di * G[i * DD + f];
    float acc1 = 0.f, acc2 = 0.f, acc3 = 0.f;

    int s = g_off[i];
    int n = g_cnt[i];
    int p = 0;
    for (; p + 4 <= n; p += 4) {
        int   i0 = g_src[s + p + 0], i1 = g_src[s + p + 1];
        int   i2 = g_src[s + p + 2], i3 = g_src[s + p + 3];
        float w0 = g_wn[s + p + 0],  w1 = g_wn[s + p + 1];
        float w2 = g_wn[s + p + 2],  w3 = g_wn[s + p + 3];
        acc0 += w0 * G[i0 * DD + f];
        acc1 += w1 * G[i1 * DD + f];
        acc2 += w2 * G[i2 * DD + f];
        acc3 += w3 * G[i3 * DD + f];
    }
    for (; p < n; p++)
        acc0 += g_wn[s + p] * G[g_src[s + p] * DD + f];

    float h2 = ((acc0 + acc1) + (acc2 + acc3)) + b1[f];
    out[i * DD + f] = (emb[i * DD + f] + g_h1[i * DD + f] + h2) * (1.0f / 3.0f);
}

// ---------------- launch -----------------------------------------------------
extern "C" void kernel_launch(void* const* d_in, const int* in_sizes, int n_in,
                              void* d_out, int out_size) {
    const float* emb   = (const float*)d_in[0];
    const int*   ei    = (const int*)  d_in[1];
    const float* ew    = (const float*)d_in[2];
    const float* W0    = (const float*)d_in[3];
    const float* b0    = (const float*)d_in[4];
    const float* W1    = (const float*)d_in[5];
    const float* b1    = (const float*)d_in[6];
    const float* gamma = (const float*)d_in[7];
    const float* beta  = (const float*)d_in[8];
    const float* mean  = (const float*)d_in[9];
    const float* var   = (const float*)d_in[10];
    float* out = (float*)d_out;

    const int* row = ei;        // edge_index[0]
    const int* col = ei + EE;   // edge_index[1]

    const int NB_N = (NN + 255) / 256;
    const int NB_E = (EE + 255) / 256;

    k_init   <<<NB_N, 256>>>();
    k_deg    <<<NB_E, 256>>>(col, ew);
    k_bsum   <<<NSCAN_BLK, 256>>>();
    k_bscan  <<<1, 256>>>();
    k_scan3  <<<NSCAN_BLK, 256>>>();
    k_scatter<<<NB_E, 256>>>(row, col, ew);

    dim3 ggrid((NN + 127) / 128, 2);
    k_gemm<<<ggrid, 256>>>(emb, W0, 0);          // g_h = emb @ W0
    k_agg1<<<NN, DD>>>(b0, gamma, beta, mean, var);
    k_gemm<<<ggrid, 256>>>(nullptr, W1, 1);      // g_g = g_h1 @ W1
    k_agg2<<<NN, DD>>>(emb, b1, out);
}